// round 1
// baseline (speedup 1.0000x reference)
#include <cuda_runtime.h>
#include <cuda_bf16.h>
#include <mma.h>
#include <math.h>

using namespace nvcuda;

// Problem constants
#define B_ 2
#define S_ 1024
#define H_ 2048
#define NH_ 16
#define HD_ 128
#define L_ 4
#define DM_ 2048   // NH_*HD_
#define KD_ 2048   // GEMM K dim (H_)

// ---------------- scratch (device globals; no runtime allocation) ----------------
__device__ float g_Q[(size_t)B_ * NH_ * S_ * HD_];            // [b][nh][s][hd]
__device__ float g_K[(size_t)L_ * B_ * NH_ * S_ * HD_];       // [l*B+b][nh][s][hd]
__device__ float g_V[(size_t)L_ * B_ * NH_ * S_ * HD_];
__device__ float g_lo[(size_t)L_ * B_ * S_ * DM_];            // [l][b][s][dm]
__device__ float g_ctx[(size_t)B_ * S_ * DM_];                // [b][s][dm]
__device__ float g_part[B_ * 16 * L_];
__device__ float g_w[B_ * L_];

// ---------------- gate: layer_w = softmax(mean_s(hidden) @ Wg) ----------------
__global__ void gate_partial(const float* __restrict__ hs, const float* __restrict__ Wg) {
    int b = blockIdx.y, ch = blockIdx.x, t = threadIdx.x;
    float part[4] = {0.f, 0.f, 0.f, 0.f};
    for (int h = t; h < H_; h += 256) {
        float sum = 0.f;
        const float* p = hs + (size_t)b * S_ * H_ + (size_t)ch * 64 * H_ + h;
#pragma unroll 8
        for (int s = 0; s < 64; s++) sum += p[(size_t)s * H_];
        float mn = sum * (1.f / (float)S_);
#pragma unroll
        for (int l = 0; l < 4; l++) part[l] += mn * Wg[h * 4 + l];
    }
    __shared__ float red[4][256];
#pragma unroll
    for (int l = 0; l < 4; l++) red[l][t] = part[l];
    __syncthreads();
    for (int st = 128; st > 0; st >>= 1) {
        if (t < st) {
#pragma unroll
            for (int l = 0; l < 4; l++) red[l][t] += red[l][t + st];
        }
        __syncthreads();
    }
    if (t < 4) g_part[(b * 16 + ch) * 4 + t] = red[t][0];
}

__global__ void gate_final() {
    // single thread; trivial work
    for (int b = 0; b < B_; b++) {
        float v[4];
        for (int l = 0; l < 4; l++) {
            float s = 0.f;
            for (int ch = 0; ch < 16; ch++) s += g_part[(b * 16 + ch) * 4 + l];
            v[l] = s;
        }
        float mx = fmaxf(fmaxf(v[0], v[1]), fmaxf(v[2], v[3]));
        float e[4], sum = 0.f;
        for (int l = 0; l < 4; l++) { e[l] = expf(v[l] - mx); sum += e[l]; }
        for (int l = 0; l < 4; l++) g_w[b * 4 + l] = e[l] / sum;
    }
}

// ---------------- TF32 WMMA GEMM: C[M,2048] = A[M,2048] @ W[2048,2048] + bias ----------------
// MODE 0: plain row-major output. MODE 1: scatter to [grp][nh][s][hd] (grp = row>>10).
template <int MODE>
__global__ __launch_bounds__(128)
void gemm_tf32(const float* __restrict__ A, const float* __restrict__ W,
               const float* __restrict__ bias, float* __restrict__ out) {
    __shared__ float sA[64][36];
    __shared__ float sB[32][68];
    __shared__ float sC[64][68];

    const int t = threadIdx.x;
    const int warp = t >> 5;
    const int wr = warp >> 1, wc = warp & 1;
    const int m0 = blockIdx.y * 64, n0 = blockIdx.x * 64;

    wmma::fragment<wmma::accumulator, 16, 16, 8, float> c[2][2];
#pragma unroll
    for (int i = 0; i < 2; i++)
#pragma unroll
        for (int j = 0; j < 2; j++) wmma::fill_fragment(c[i][j], 0.f);

    for (int kk = 0; kk < KD_; kk += 32) {
#pragma unroll
        for (int i = 0; i < 4; i++) {
            int id4 = t + i * 128;
            int r = id4 >> 3, c4 = (id4 & 7) * 4;
            *(float4*)&sA[r][c4] = *(const float4*)&A[(size_t)(m0 + r) * KD_ + kk + c4];
        }
#pragma unroll
        for (int i = 0; i < 4; i++) {
            int id4 = t + i * 128;
            int r = id4 >> 4, c4 = (id4 & 15) * 4;
            *(float4*)&sB[r][c4] = *(const float4*)&W[(size_t)(kk + r) * 2048 + n0 + c4];
        }
        __syncthreads();
#pragma unroll
        for (int ks = 0; ks < 4; ks++) {
            wmma::fragment<wmma::matrix_a, 16, 16, 8, wmma::precision::tf32, wmma::row_major> a[2];
            wmma::fragment<wmma::matrix_b, 16, 16, 8, wmma::precision::tf32, wmma::row_major> bf[2];
#pragma unroll
            for (int i = 0; i < 2; i++) {
                wmma::load_matrix_sync(a[i], &sA[wr * 32 + i * 16][ks * 8], 36);
#pragma unroll
                for (int e = 0; e < a[i].num_elements; e++)
                    a[i].x[e] = wmma::__float_to_tf32(a[i].x[e]);
            }
#pragma unroll
            for (int j = 0; j < 2; j++) {
                wmma::load_matrix_sync(bf[j], &sB[ks * 8][wc * 32 + j * 16], 68);
#pragma unroll
                for (int e = 0; e < bf[j].num_elements; e++)
                    bf[j].x[e] = wmma::__float_to_tf32(bf[j].x[e]);
            }
#pragma unroll
            for (int i = 0; i < 2; i++)
#pragma unroll
                for (int j = 0; j < 2; j++)
                    wmma::mma_sync(c[i][j], a[i], bf[j], c[i][j]);
        }
        __syncthreads();
    }

#pragma unroll
    for (int i = 0; i < 2; i++)
#pragma unroll
        for (int j = 0; j < 2; j++)
            wmma::store_matrix_sync(&sC[wr * 32 + i * 16][wc * 32 + j * 16], c[i][j], 68,
                                    wmma::mem_row_major);
    __syncthreads();

#pragma unroll
    for (int i = 0; i < 32; i++) {
        int idx = t + i * 128;
        int r = idx >> 6, cc = idx & 63;
        float v = sC[r][cc] + bias[n0 + cc];
        int row = m0 + r, gcol = n0 + cc;
        if (MODE == 0) {
            out[(size_t)row * 2048 + gcol] = v;
        } else {
            int grp = row >> 10, s = row & 1023;
            int nh = gcol >> 7, hd = gcol & 127;
            out[(((size_t)grp * NH_ + nh) * S_ + s) * HD_ + hd] = v;
        }
    }
}

// ---------------- RoPE (in place, [g][s][hd] layout) ----------------
__global__ void rope_kernel(int which, int total) {
    int idx = blockIdx.x * 256 + threadIdx.x;
    if (idx >= total) return;
    float* p = which ? g_K : g_Q;
    int i = idx & 63;
    int s = (idx >> 6) & 1023;
    size_t base = ((size_t)(idx >> 6)) * HD_;
    double inv = pow(10000.0, -(double)i / 64.0);
    double ang = (double)s * inv;
    float cth = (float)cos(ang), sth = (float)sin(ang);
    float x1 = p[base + i], x2 = p[base + i + 64];
    p[base + i]      = x1 * cth - x2 * sth;
    p[base + i + 64] = x2 * cth + x1 * sth;
}

// ---------------- flash attention: per (l,b,nh,q-tile of 64) ----------------
__global__ __launch_bounds__(128)
void attn_kernel() {
    extern __shared__ float dyn[];
    float* sK = dyn;                 // 64*132
    float* sV = sK + 64 * 132;       // 64*132
    float* sS = sV + 64 * 132;       // 64*72
    float* sO = sS + 64 * 72;        // 64*132
    float* smx = sO + 64 * 132;      // 64
    float* sls = smx + 64;           // 64

    const int t = threadIdx.x, warp = t >> 5;
    const int qt = blockIdx.x, nh = blockIdx.y, lb = blockIdx.z;

    const float* Qg = g_Q + ((size_t)((lb & 1) * NH_ + nh) * S_ + qt * 64) * HD_;
    const float* Kg = g_K + (size_t)(lb * NH_ + nh) * S_ * HD_;
    const float* Vg = g_V + (size_t)(lb * NH_ + nh) * S_ * HD_;

    for (int i = t; i < 64; i += 128) { smx[i] = -1e30f; sls[i] = 0.f; }
    for (int i = t; i < 64 * 132; i += 128) sO[i] = 0.f;
    __syncthreads();

    for (int kt = 0; kt < 16; kt++) {
        // stage K,V tiles [64][128] -> smem (padded 132)
#pragma unroll
        for (int i = 0; i < 16; i++) {
            int id4 = t + i * 128;
            int r = id4 >> 5, c4 = (id4 & 31) * 4;
            *(float4*)&sK[r * 132 + c4] = *(const float4*)&Kg[(size_t)(kt * 64 + r) * HD_ + c4];
            *(float4*)&sV[r * 132 + c4] = *(const float4*)&Vg[(size_t)(kt * 64 + r) * HD_ + c4];
        }
        __syncthreads();

        // S = Q @ K^T * scale   (warp w -> rows [16w,16w+16), cols [0,64))
        {
            wmma::fragment<wmma::accumulator, 16, 16, 8, float> cf[4];
#pragma unroll
            for (int n = 0; n < 4; n++) wmma::fill_fragment(cf[n], 0.f);
#pragma unroll
            for (int kd = 0; kd < 16; kd++) {
                wmma::fragment<wmma::matrix_a, 16, 16, 8, wmma::precision::tf32, wmma::row_major> a;
                wmma::load_matrix_sync(a, Qg + (size_t)(warp * 16) * HD_ + kd * 8, HD_);
#pragma unroll
                for (int e = 0; e < a.num_elements; e++) a.x[e] = wmma::__float_to_tf32(a.x[e]);
#pragma unroll
                for (int n = 0; n < 4; n++) {
                    wmma::fragment<wmma::matrix_b, 16, 16, 8, wmma::precision::tf32, wmma::col_major> bf;
                    wmma::load_matrix_sync(bf, &sK[(n * 16) * 132 + kd * 8], 132);
#pragma unroll
                    for (int e = 0; e < bf.num_elements; e++) bf.x[e] = wmma::__float_to_tf32(bf.x[e]);
                    wmma::mma_sync(cf[n], a, bf, cf[n]);
                }
            }
            const float scale = 0.08838834764831845f; // 1/sqrt(128)
#pragma unroll
            for (int n = 0; n < 4; n++) {
#pragma unroll
                for (int e = 0; e < cf[n].num_elements; e++) cf[n].x[e] *= scale;
                wmma::store_matrix_sync(&sS[(warp * 16) * 72 + n * 16], cf[n], 72, wmma::mem_row_major);
            }
        }
        __syncthreads();

        // online softmax update (2 threads per row; each covers 32 score cols, 64 O cols)
        {
            int r = t >> 1, hf = t & 1;
            float* srow = &sS[r * 72 + hf * 32];
            float mx = -1e30f;
#pragma unroll
            for (int c = 0; c < 32; c++) mx = fmaxf(mx, srow[c]);
            mx = fmaxf(mx, __shfl_xor_sync(0xffffffffu, mx, 1));
            float mold = smx[r];
            float mnew = fmaxf(mold, mx);
            float fac = __expf(mold - mnew);
            float ps = 0.f;
#pragma unroll
            for (int c = 0; c < 32; c++) {
                float e = __expf(srow[c] - mnew);
                srow[c] = e;
                ps += e;
            }
            ps += __shfl_xor_sync(0xffffffffu, ps, 1);
            float* orow = &sO[r * 132 + hf * 64];
#pragma unroll
            for (int c = 0; c < 64; c++) orow[c] *= fac;
            if (hf == 0) { sls[r] = sls[r] * fac + ps; smx[r] = mnew; }
        }
        __syncthreads();

        // O += P @ V   (warp w -> rows [16w,16w+16), cols 0..128)
        {
            wmma::fragment<wmma::matrix_a, 16, 16, 8, wmma::precision::tf32, wmma::row_major> a[8];
#pragma unroll
            for (int kd = 0; kd < 8; kd++) {
                wmma::load_matrix_sync(a[kd], &sS[(warp * 16) * 72 + kd * 8], 72);
#pragma unroll
                for (int e = 0; e < a[kd].num_elements; e++)
                    a[kd].x[e] = wmma::__float_to_tf32(a[kd].x[e]);
            }
#pragma unroll
            for (int n = 0; n < 8; n++) {
                wmma::fragment<wmma::accumulator, 16, 16, 8, float> co;
                wmma::load_matrix_sync(co, &sO[(warp * 16) * 132 + n * 16], 132, wmma::mem_row_major);
#pragma unroll
                for (int kd = 0; kd < 8; kd++) {
                    wmma::fragment<wmma::matrix_b, 16, 16, 8, wmma::precision::tf32, wmma::row_major> bf;
                    wmma::load_matrix_sync(bf, &sV[(kd * 8) * 132 + n * 16], 132);
#pragma unroll
                    for (int e = 0; e < bf.num_elements; e++) bf.x[e] = wmma::__float_to_tf32(bf.x[e]);
                    wmma::mma_sync(co, a[kd], bf, co);
                }
                wmma::store_matrix_sync(&sO[(warp * 16) * 132 + n * 16], co, 132, wmma::mem_row_major);
            }
        }
        __syncthreads();
    }

    // normalize & write to g_lo[l][b][s][dm]
    {
        int r = t >> 1, hf = t & 1;
        float inv = 1.f / sls[r];
        size_t obase = ((size_t)lb * S_ + qt * 64 + r) * DM_ + nh * HD_ + hf * 64;
#pragma unroll
        for (int c = 0; c < 64; c++) g_lo[obase + c] = sO[r * 132 + hf * 64 + c] * inv;
    }
}

// ---------------- combine: ctx = sum_l w[b,l] * lo[l] ----------------
__global__ void combine_kernel() {
    int idx = blockIdx.x * 256 + threadIdx.x;
    if (idx >= B_ * S_ * DM_) return;
    int b = idx >> 21; // S_*DM_ = 2^21
    float acc = 0.f;
#pragma unroll
    for (int l = 0; l < 4; l++)
        acc += g_w[b * 4 + l] * g_lo[(size_t)l * ((size_t)B_ * S_ * DM_) + idx];
    g_ctx[idx] = acc;
}

// ---------------- host launch ----------------
extern "C" void kernel_launch(void* const* d_in, const int* in_sizes, int n_in,
                              void* d_out, int out_size) {
    (void)in_sizes; (void)n_in; (void)out_size;
    const float* hs   = (const float*)d_in[0];
    const float* prev = (const float*)d_in[1];
    const float* Wq   = (const float*)d_in[2];
    const float* bq   = (const float*)d_in[3];
    const float* Wk   = (const float*)d_in[4];
    const float* bk   = (const float*)d_in[5];
    const float* Wv   = (const float*)d_in[6];
    const float* bv   = (const float*)d_in[7];
    const float* Wo   = (const float*)d_in[8];
    const float* bo   = (const float*)d_in[9];
    const float* Wg   = (const float*)d_in[10];
    float* out = (float*)d_out;

    void* pQ; void* pK; void* pV; void* pCtx;
    cudaGetSymbolAddress(&pQ, g_Q);
    cudaGetSymbolAddress(&pK, g_K);
    cudaGetSymbolAddress(&pV, g_V);
    cudaGetSymbolAddress(&pCtx, g_ctx);

    const int ATTN_SMEM = (64 * 132 * 3 + 64 * 72 + 128) * 4; // 120320 B
    cudaFuncSetAttribute(attn_kernel, cudaFuncAttributeMaxDynamicSharedMemorySize, ATTN_SMEM);

    // 1. gate
    gate_partial<<<dim3(16, B_), 256>>>(hs, Wg);
    gate_final<<<1, 1>>>();

    // 2. projections (scatter into [grp][nh][s][hd])
    gemm_tf32<1><<<dim3(32, 32), 128>>>(hs, Wq, bq, (float*)pQ);
    gemm_tf32<1><<<dim3(32, 128), 128>>>(prev, Wk, bk, (float*)pK);
    gemm_tf32<1><<<dim3(32, 128), 128>>>(prev, Wv, bv, (float*)pV);

    // 3. RoPE on Q and K
    {
        int totQ = B_ * NH_ * S_ * 64;      // 2,097,152
        int totK = L_ * B_ * NH_ * S_ * 64; // 8,388,608
        rope_kernel<<<(totQ + 255) / 256, 256>>>(0, totQ);
        rope_kernel<<<(totK + 255) / 256, 256>>>(1, totK);
    }

    // 4. attention
    attn_kernel<<<dim3(S_ / 64, NH_, L_ * B_), 128, ATTN_SMEM>>>();

    // 5. combine
    combine_kernel<<<(B_ * S_ * DM_ + 255) / 256, 256>>>();

    // 6. output projection
    gemm_tf32<0><<<dim3(32, 32), 128>>>((const float*)pCtx, Wo, bo, out);
}

// round 4
// speedup vs baseline: 1.5391x; 1.5391x over previous
#include <cuda_runtime.h>
#include <cuda_bf16.h>
#include <mma.h>
#include <math.h>

using namespace nvcuda;

// Problem constants
#define B_ 2
#define S_ 1024
#define H_ 2048
#define NH_ 16
#define HD_ 128
#define L_ 4
#define DM_ 2048
#define KD_ 2048

// ---------------- scratch ----------------
__device__ float g_Q[(size_t)B_ * NH_ * S_ * HD_];
__device__ float g_K[(size_t)L_ * B_ * NH_ * S_ * HD_];
__device__ float g_V[(size_t)L_ * B_ * NH_ * S_ * HD_];
__device__ float g_lo[(size_t)L_ * B_ * S_ * DM_];
__device__ float g_ctx[(size_t)B_ * S_ * DM_];
__device__ float g_part[B_ * 16 * L_];
__device__ float g_w[B_ * L_];

__device__ __forceinline__ float4 round_tf32_4(float4 v) {
    v.x = wmma::__float_to_tf32(v.x);
    v.y = wmma::__float_to_tf32(v.y);
    v.z = wmma::__float_to_tf32(v.z);
    v.w = wmma::__float_to_tf32(v.w);
    return v;
}

// ---------------- gate ----------------
__global__ void gate_partial(const float* __restrict__ hs, const float* __restrict__ Wg) {
    int b = blockIdx.y, ch = blockIdx.x, t = threadIdx.x;
    float part[4] = {0.f, 0.f, 0.f, 0.f};
    for (int h = t; h < H_; h += 256) {
        float sum = 0.f;
        const float* p = hs + (size_t)b * S_ * H_ + (size_t)ch * 64 * H_ + h;
#pragma unroll 8
        for (int s = 0; s < 64; s++) sum += p[(size_t)s * H_];
        float mn = sum * (1.f / (float)S_);
#pragma unroll
        for (int l = 0; l < 4; l++) part[l] += mn * Wg[h * 4 + l];
    }
    __shared__ float red[4][256];
#pragma unroll
    for (int l = 0; l < 4; l++) red[l][t] = part[l];
    __syncthreads();
    for (int st = 128; st > 0; st >>= 1) {
        if (t < st) {
#pragma unroll
            for (int l = 0; l < 4; l++) red[l][t] += red[l][t + st];
        }
        __syncthreads();
    }
    if (t < 4) g_part[(b * 16 + ch) * 4 + t] = red[t][0];
}

__global__ void gate_final() {
    for (int b = 0; b < B_; b++) {
        float v[4];
        for (int l = 0; l < 4; l++) {
            float s = 0.f;
            for (int ch = 0; ch < 16; ch++) s += g_part[(b * 16 + ch) * 4 + l];
            v[l] = s;
        }
        float mx = fmaxf(fmaxf(v[0], v[1]), fmaxf(v[2], v[3]));
        float e[4], sum = 0.f;
        for (int l = 0; l < 4; l++) { e[l] = expf(v[l] - mx); sum += e[l]; }
        for (int l = 0; l < 4; l++) g_w[b * 4 + l] = e[l] / sum;
    }
}

// ---------------- TF32 GEMM v2: 128x128 tile, 256 thr, double-buffered ----------------
// C[M,2048] = A[M,2048] @ W[2048,2048] + bias
// MODE 0: row-major out. MODE 1: scatter to [grp][nh][s][hd] (grp = row>>10).
#define SA_STRIDE 36     // 32 + pad
#define SB_STRIDE 132    // 128 + pad
#define SA_BUF (128 * SA_STRIDE)
#define SB_BUF (32 * SB_STRIDE)
#define GEMM_SMEM_BYTES ((2 * SA_BUF + 2 * SB_BUF) * 4)   // 70656

template <int MODE>
__global__ __launch_bounds__(256)
void gemm_tf32(const float* __restrict__ A, const float* __restrict__ W,
               const float* __restrict__ bias, float* __restrict__ out) {
    extern __shared__ float dg[];
    float* sA = dg;                 // 2 * 128*36
    float* sB = dg + 2 * SA_BUF;    // 2 * 32*132

    const int t = threadIdx.x;
    const int warp = t >> 5;
    const int wr = warp & 1;        // 0..1 -> 64-row group
    const int wc = warp >> 1;       // 0..3 -> 32-col group
    const int m0 = blockIdx.y * 128, n0 = blockIdx.x * 128;

    // per-thread load coords
    int rA[4], cA[4], rB[4], cB[4];
#pragma unroll
    for (int i = 0; i < 4; i++) {
        int f = t + i * 256;
        rA[i] = f >> 3;  cA[i] = (f & 7) * 4;     // A tile 128x32
        rB[i] = f >> 5;  cB[i] = (f & 31) * 4;    // B tile 32x128
    }

    wmma::fragment<wmma::accumulator, 16, 16, 8, float> c[4][2];
#pragma unroll
    for (int i = 0; i < 4; i++)
#pragma unroll
        for (int j = 0; j < 2; j++) wmma::fill_fragment(c[i][j], 0.f);

    float4 va[4], vb[4];
    // prologue: chunk 0
#pragma unroll
    for (int i = 0; i < 4; i++) {
        va[i] = *(const float4*)&A[(size_t)(m0 + rA[i]) * KD_ + cA[i]];
        vb[i] = *(const float4*)&W[(size_t)rB[i] * 2048 + n0 + cB[i]];
    }
#pragma unroll
    for (int i = 0; i < 4; i++) {
        *(float4*)&sA[rA[i] * SA_STRIDE + cA[i]] = round_tf32_4(va[i]);
        *(float4*)&sB[rB[i] * SB_STRIDE + cB[i]] = round_tf32_4(vb[i]);
    }
    __syncthreads();

    for (int kk = 0; kk < 64; kk++) {
        const int cur = kk & 1;
        if (kk + 1 < 64) {
            const int k1 = (kk + 1) * 32;
#pragma unroll
            for (int i = 0; i < 4; i++) {
                va[i] = *(const float4*)&A[(size_t)(m0 + rA[i]) * KD_ + k1 + cA[i]];
                vb[i] = *(const float4*)&W[(size_t)(k1 + rB[i]) * 2048 + n0 + cB[i]];
            }
        }
        // compute on buffer cur (values already tf32-rounded; no per-elem convert)
        const float* pA = sA + cur * SA_BUF;
        const float* pB = sB + cur * SB_BUF;
#pragma unroll
        for (int ks = 0; ks < 4; ks++) {
            wmma::fragment<wmma::matrix_a, 16, 16, 8, wmma::precision::tf32, wmma::row_major> a[4];
            wmma::fragment<wmma::matrix_b, 16, 16, 8, wmma::precision::tf32, wmma::row_major> bfr[2];
#pragma unroll
            for (int i = 0; i < 4; i++)
                wmma::load_matrix_sync(a[i], pA + (wr * 64 + i * 16) * SA_STRIDE + ks * 8, SA_STRIDE);
#pragma unroll
            for (int j = 0; j < 2; j++)
                wmma::load_matrix_sync(bfr[j], pB + (ks * 8) * SB_STRIDE + wc * 32 + j * 16, SB_STRIDE);
#pragma unroll
            for (int i = 0; i < 4; i++)
#pragma unroll
                for (int j = 0; j < 2; j++)
                    wmma::mma_sync(c[i][j], a[i], bfr[j], c[i][j]);
        }
        if (kk + 1 < 64) {
            const int nb = (kk + 1) & 1;
#pragma unroll
            for (int i = 0; i < 4; i++) {
                *(float4*)&sA[nb * SA_BUF + rA[i] * SA_STRIDE + cA[i]] = round_tf32_4(va[i]);
                *(float4*)&sB[nb * SB_BUF + rB[i] * SB_STRIDE + cB[i]] = round_tf32_4(vb[i]);
            }
        }
        __syncthreads();
    }

    // epilogue: stage C in smem (reuse dg), then vectorized global writes
    float* sC = dg;  // 128 * 132 = 16896 floats <= 17664 available
#pragma unroll
    for (int i = 0; i < 4; i++)
#pragma unroll
        for (int j = 0; j < 2; j++)
            wmma::store_matrix_sync(&sC[(wr * 64 + i * 16) * 132 + wc * 32 + j * 16],
                                    c[i][j], 132, wmma::mem_row_major);
    __syncthreads();

#pragma unroll
    for (int i = 0; i < 16; i++) {
        int f = t + i * 256;
        int r = f >> 5, c4 = (f & 31) * 4;
        float4 v = *(float4*)&sC[r * 132 + c4];
        v.x += bias[n0 + c4 + 0];
        v.y += bias[n0 + c4 + 1];
        v.z += bias[n0 + c4 + 2];
        v.w += bias[n0 + c4 + 3];
        int row = m0 + r;
        if (MODE == 0) {
            *(float4*)&out[(size_t)row * 2048 + n0 + c4] = v;
        } else {
            int grp = row >> 10, s = row & 1023;
            int nh = n0 >> 7;              // n0 multiple of 128
            *(float4*)&out[(((size_t)grp * NH_ + nh) * S_ + s) * HD_ + c4] = v;
        }
    }
}

// ---------------- RoPE (fp32) ----------------
__global__ void rope_kernel(int which, int total) {
    int idx = blockIdx.x * 256 + threadIdx.x;
    if (idx >= total) return;
    float* p = which ? g_K : g_Q;
    int i = idx & 63;
    int s = (idx >> 6) & 1023;
    size_t base = ((size_t)(idx >> 6)) * HD_;
    // inv_freq = 10000^(-i/64)
    float inv = __expf(-(float)i * (9.210340371976184f / 64.0f)); // ln(10000)=9.2103...
    float ang = (float)s * inv;
    float sth, cth;
    sincosf(ang, &sth, &cth);
    float x1 = p[base + i], x2 = p[base + i + 64];
    p[base + i]      = x1 * cth - x2 * sth;
    p[base + i + 64] = x2 * cth + x1 * sth;
}

// ---------------- flash attention v2: q-tile 128, 8 warps, Q in registers ----------------
#define ATTN_SMEM_FLOATS (8448 + 8448 + 8704 + 16896 + 256)
#define ATTN_SMEM_BYTES (ATTN_SMEM_FLOATS * 4)   // 171008

__global__ __launch_bounds__(256)
void attn_kernel() {
    extern __shared__ float dyn[];
    float* sK  = dyn;                  // 64*132
    float* sV  = sK + 8448;            // 64*132
    float* sS  = sV + 8448;            // 128*68
    float* sO  = sS + 8704;            // 128*132
    float* smx = sO + 16896;           // 128
    float* sls = smx + 128;            // 128

    const int t = threadIdx.x, warp = t >> 5;
    const int qt = blockIdx.x, nh = blockIdx.y, lb = blockIdx.z;

    const float* Qg = g_Q + ((size_t)((lb & 1) * NH_ + nh) * S_ + qt * 128 + warp * 16) * HD_;
    const float* Kg = g_K + (size_t)(lb * NH_ + nh) * S_ * HD_;
    const float* Vg = g_V + (size_t)(lb * NH_ + nh) * S_ * HD_;

    // Q fragments resident in registers, pre-scaled + tf32-rounded
    wmma::fragment<wmma::matrix_a, 16, 16, 8, wmma::precision::tf32, wmma::row_major> qf[16];
    const float scale = 0.08838834764831845f; // 1/sqrt(128)
#pragma unroll
    for (int kd = 0; kd < 16; kd++) {
        wmma::load_matrix_sync(qf[kd], Qg + kd * 8, HD_);
#pragma unroll
        for (int e = 0; e < qf[kd].num_elements; e++)
            qf[kd].x[e] = wmma::__float_to_tf32(qf[kd].x[e] * scale);
    }

    for (int i = t; i < 128; i += 256) { smx[i] = -1e30f; sls[i] = 0.f; }
    for (int i = t; i < 16896; i += 256) sO[i] = 0.f;
    __syncthreads();

    for (int kt = 0; kt < 16; kt++) {
        // stage K,V tiles [64][128], tf32-rounded
#pragma unroll
        for (int i = 0; i < 8; i++) {
            int f = t + i * 256;
            int r = f >> 5, c4 = (f & 31) * 4;
            float4 kv = *(const float4*)&Kg[(size_t)(kt * 64 + r) * HD_ + c4];
            float4 vv = *(const float4*)&Vg[(size_t)(kt * 64 + r) * HD_ + c4];
            *(float4*)&sK[r * 132 + c4] = round_tf32_4(kv);
            *(float4*)&sV[r * 132 + c4] = round_tf32_4(vv);
        }
        __syncthreads();

        // S = Qs @ K^T  (warp -> rows [16w,16w+16), cols [0,64))
        {
            wmma::fragment<wmma::accumulator, 16, 16, 8, float> cf[4];
#pragma unroll
            for (int n = 0; n < 4; n++) wmma::fill_fragment(cf[n], 0.f);
#pragma unroll
            for (int kd = 0; kd < 16; kd++) {
#pragma unroll
                for (int n = 0; n < 4; n++) {
                    wmma::fragment<wmma::matrix_b, 16, 16, 8, wmma::precision::tf32, wmma::col_major> bf;
                    wmma::load_matrix_sync(bf, &sK[(n * 16) * 132 + kd * 8], 132);
                    wmma::mma_sync(cf[n], qf[kd], bf, cf[n]);
                }
            }
#pragma unroll
            for (int n = 0; n < 4; n++)
                wmma::store_matrix_sync(&sS[(warp * 16) * 68 + n * 16], cf[n], 68, wmma::mem_row_major);
        }
        __syncthreads();

        // online softmax (2 threads/row)
        {
            int r = t >> 1, hf = t & 1;
            float* srow = &sS[r * 68 + hf * 32];
            float mx = -1e30f;
#pragma unroll
            for (int c = 0; c < 32; c++) mx = fmaxf(mx, srow[c]);
            mx = fmaxf(mx, __shfl_xor_sync(0xffffffffu, mx, 1));
            float mold = smx[r];
            float mnew = fmaxf(mold, mx);
            float fac = __expf(mold - mnew);
            float ps = 0.f;
#pragma unroll
            for (int c = 0; c < 32; c++) {
                float e = __expf(srow[c] - mnew);
                srow[c] = wmma::__float_to_tf32(e);   // P pre-rounded for mma
                ps += e;
            }
            ps += __shfl_xor_sync(0xffffffffu, ps, 1);
            float* orow = &sO[r * 132 + hf * 64];
#pragma unroll
            for (int c = 0; c < 64; c++) orow[c] *= fac;
            if (hf == 0) { sls[r] = sls[r] * fac + ps; smx[r] = mnew; }
        }
        __syncthreads();

        // O += P @ V
        {
            wmma::fragment<wmma::matrix_a, 16, 16, 8, wmma::precision::tf32, wmma::row_major> pf[8];
#pragma unroll
            for (int kd = 0; kd < 8; kd++)
                wmma::load_matrix_sync(pf[kd], &sS[(warp * 16) * 68 + kd * 8], 68);
#pragma unroll
            for (int n = 0; n < 8; n++) {
                wmma::fragment<wmma::accumulator, 16, 16, 8, float> co;
                wmma::load_matrix_sync(co, &sO[(warp * 16) * 132 + n * 16], 132, wmma::mem_row_major);
#pragma unroll
                for (int kd = 0; kd < 8; kd++) {
                    wmma::fragment<wmma::matrix_b, 16, 16, 8, wmma::precision::tf32, wmma::row_major> bf;
                    wmma::load_matrix_sync(bf, &sV[(kd * 8) * 132 + n * 16], 132);
                    wmma::mma_sync(co, pf[kd], bf, co);
                }
                wmma::store_matrix_sync(&sO[(warp * 16) * 132 + n * 16], co, 132, wmma::mem_row_major);
            }
        }
        __syncthreads();
    }

    // normalize & write g_lo[l][b][s][dm]
    {
        int r = t >> 1, hf = t & 1;
        float inv = 1.f / sls[r];
        size_t obase = ((size_t)lb * S_ + qt * 128 + r) * DM_ + nh * HD_ + hf * 64;
#pragma unroll
        for (int c4 = 0; c4 < 64; c4 += 4) {
            float4 v = *(float4*)&sO[r * 132 + hf * 64 + c4];
            v.x *= inv; v.y *= inv; v.z *= inv; v.w *= inv;
            *(float4*)&g_lo[obase + c4] = v;
        }
    }
}

// ---------------- combine ----------------
__global__ void combine_kernel() {
    int idx = blockIdx.x * 256 + threadIdx.x;
    if (idx >= B_ * S_ * DM_) return;
    int b = idx >> 21;
    float acc = 0.f;
#pragma unroll
    for (int l = 0; l < 4; l++)
        acc += g_w[b * 4 + l] * g_lo[(size_t)l * ((size_t)B_ * S_ * DM_) + idx];
    g_ctx[idx] = acc;
}

// ---------------- host launch ----------------
extern "C" void kernel_launch(void* const* d_in, const int* in_sizes, int n_in,
                              void* d_out, int out_size) {
    (void)in_sizes; (void)n_in; (void)out_size;
    const float* hs   = (const float*)d_in[0];
    const float* prev = (const float*)d_in[1];
    const float* Wq   = (const float*)d_in[2];
    const float* bq   = (const float*)d_in[3];
    const float* Wk   = (const float*)d_in[4];
    const float* bk   = (const float*)d_in[5];
    const float* Wv   = (const float*)d_in[6];
    const float* bv   = (const float*)d_in[7];
    const float* Wo   = (const float*)d_in[8];
    const float* bo   = (const float*)d_in[9];
    const float* Wg   = (const float*)d_in[10];
    float* out = (float*)d_out;

    void* pQ; void* pK; void* pV; void* pCtx;
    cudaGetSymbolAddress(&pQ, g_Q);
    cudaGetSymbolAddress(&pK, g_K);
    cudaGetSymbolAddress(&pV, g_V);
    cudaGetSymbolAddress(&pCtx, g_ctx);

    cudaFuncSetAttribute(gemm_tf32<0>, cudaFuncAttributeMaxDynamicSharedMemorySize, GEMM_SMEM_BYTES);
    cudaFuncSetAttribute(gemm_tf32<1>, cudaFuncAttributeMaxDynamicSharedMemorySize, GEMM_SMEM_BYTES);
    cudaFuncSetAttribute(attn_kernel, cudaFuncAttributeMaxDynamicSharedMemorySize, ATTN_SMEM_BYTES);

    // 1. gate
    gate_partial<<<dim3(16, B_), 256>>>(hs, Wg);
    gate_final<<<1, 1>>>();

    // 2. projections (scatter into [grp][nh][s][hd])
    gemm_tf32<1><<<dim3(16, 16), 256, GEMM_SMEM_BYTES>>>(hs, Wq, bq, (float*)pQ);
    gemm_tf32<1><<<dim3(16, 64), 256, GEMM_SMEM_BYTES>>>(prev, Wk, bk, (float*)pK);
    gemm_tf32<1><<<dim3(16, 64), 256, GEMM_SMEM_BYTES>>>(prev, Wv, bv, (float*)pV);

    // 3. RoPE on Q and K
    {
        int totQ = B_ * NH_ * S_ * 64;
        int totK = L_ * B_ * NH_ * S_ * 64;
        rope_kernel<<<(totQ + 255) / 256, 256>>>(0, totQ);
        rope_kernel<<<(totK + 255) / 256, 256>>>(1, totK);
    }

    // 4. attention: (S/128, NH, L*B)
    attn_kernel<<<dim3(S_ / 128, NH_, L_ * B_), 256, ATTN_SMEM_BYTES>>>();

    // 5. combine
    combine_kernel<<<(B_ * S_ * DM_ + 255) / 256, 256>>>();

    // 6. output projection
    gemm_tf32<0><<<dim3(16, 16), 256, GEMM_SMEM_BYTES>>>((const float*)pCtx, Wo, bo, out);
}